// round 10
// baseline (speedup 1.0000x reference)
#include <cuda_runtime.h>
#include <cuda_fp16.h>

#define NN    20000
#define EE    320000
#define BB    128
#define DIN   64
#define HH    2
#define CC    64
#define LL    2
#define SLOPE 0.2f
#define EPSBN 1e-5f
#define GB    1250          // gather blocks (NN/16)

// ---------------- scratch (device globals; no allocation) ----------------
__device__ __half g_xlh[NN * 128];          // [N][128] node features fp16 (both heads)
__device__ float g_al[NN * HH];
__device__ float g_ar[NN * HH];
__device__ float g_pe[LL * EE * HH];        // ae dot + ins term, both layers
__device__ float g_h[NN * DIN];             // hidden state between layers (pre-BN)
__device__ float g_wa[LL * 3 * 128 * HH];   // folded att vectors [l][{al,ar,ae}][k][h]
__device__ float g_ins_xl[LL * BB * 128];   // ins @ W_l_bottom
__device__ float g_ins_a[LL * 3 * BB * HH]; // ins @ w_{al,ar,ae}_bottom
__device__ int   g_cnt[NN];                 // in-degree histogram (zeroed by scan each call)
__device__ int   g_start[NN + 1];           // CSR row starts
__device__ int   g_cur[NN];                 // placement cursors
__device__ int   g_csr[EE];                 // edge ids grouped by dst (sorted per bucket)
__device__ float g_bnp[GB * 64];
__device__ float g_bnp2[GB * 64];
__device__ float g_mu[64];
__device__ float g_scale[64];               // gamma * rsqrt(var + eps)

// =================================================================
// prep: [0,6) g_wa | [6,134) ins_xl | [134,140) ins_a | [140,1390) histogram
// =================================================================
__global__ __launch_bounds__(256) void prep_kernel(
    const float* __restrict__ Wl, const float* __restrict__ We,
    const float* __restrict__ attl, const float* __restrict__ attr_,
    const float* __restrict__ atte, const float* __restrict__ ins,
    const int* __restrict__ ei) {
    int bid = blockIdx.x;
    int t = threadIdx.x;
    if (bid < 6) {
        int l = bid / 3, ty = bid % 3;
        int k = t >> 1, h = t & 1;
        const float* W   = (ty == 2) ? We : Wl;
        const float* att = (ty == 0) ? attl : (ty == 1) ? attr_ : atte;
        float acc = 0.f;
#pragma unroll 8
        for (int c = 0; c < CC; c++)
            acc += W[l * 16384 + k * 128 + h * CC + c] * att[l * 128 + h * CC + c];
        g_wa[((l * 3 + ty) * 128 + k) * HH + h] = acc;
    } else if (bid < 134) {
        int idx = (bid - 6) * 256 + t;          // [0, 32768)
        int l = idx >> 14, r = idx & 16383;
        int b = r >> 7, m = r & 127;
        float acc = 0.f;
#pragma unroll 8
        for (int k = 0; k < DIN; k++)
            acc += ins[(l * BB + b) * DIN + k] * Wl[l * 16384 + (64 + k) * 128 + m];
        g_ins_xl[(l * BB + b) * 128 + m] = acc;
    } else if (bid < 140) {
        __shared__ float wb[64][2];
        int j = bid - 134;
        int l = j / 3, ty = j % 3;
        const float* W   = (ty == 2) ? We : Wl;
        const float* att = (ty == 0) ? attl : (ty == 1) ? attr_ : atte;
        if (t < 128) {
            int k = t >> 1, h = t & 1;
            float acc = 0.f;
#pragma unroll 8
            for (int c = 0; c < CC; c++)
                acc += W[l * 16384 + (64 + k) * 128 + h * CC + c] * att[l * 128 + h * CC + c];
            wb[k][h] = acc;
        }
        __syncthreads();
        int b = t >> 1, h = t & 1;
        float acc = 0.f;
#pragma unroll 8
        for (int k = 0; k < DIN; k++)
            acc += ins[(l * BB + b) * DIN + k] * wb[k][h];
        g_ins_a[((l * 3 + ty) * BB + b) * HH + h] = acc;
    } else {
        int e = (bid - 140) * 256 + t;
        atomicAdd(&g_cnt[ei[EE + e]], 1);
    }
}

// =================================================================
// scan: single block, exclusive prefix over g_cnt; writes start/cur; zeroes cnt
// =================================================================
__global__ __launch_bounds__(1024) void scan_kernel() {
    __shared__ int wsum[32];
    int t = threadIdx.x;
    int lane = t & 31, wid = t >> 5;
    int base = t * 20;
    int vals[20];
    int s = 0;
#pragma unroll
    for (int i = 0; i < 20; i++) {
        int n = base + i;
        int c = (n < NN) ? g_cnt[n] : 0;
        vals[i] = s;                // exclusive local prefix
        s += c;
    }
    int inc = s;
#pragma unroll
    for (int o = 1; o < 32; o <<= 1) {
        int u = __shfl_up_sync(0xffffffffu, inc, o);
        if (lane >= o) inc += u;
    }
    int wexcl = inc - s;
    if (lane == 31) wsum[wid] = inc;
    __syncthreads();
    if (wid == 0) {
        int v = wsum[lane];
        int inc2 = v;
#pragma unroll
        for (int o = 1; o < 32; o <<= 1) {
            int u = __shfl_up_sync(0xffffffffu, inc2, o);
            if (lane >= o) inc2 += u;
        }
        wsum[lane] = inc2 - v;      // exclusive warp offsets
    }
    __syncthreads();
    int boff = wsum[wid] + wexcl;
#pragma unroll
    for (int i = 0; i < 20; i++) {
        int n = base + i;
        if (n < NN) {
            int st = boff + vals[i];
            g_start[n] = st;
            g_cur[n] = st;
            g_cnt[n] = 0;           // ready for next call
        }
    }
    if (t == 0) g_start[NN] = EE;
}

// =================================================================
// node block body: 256 threads process 32 nodes (two half-groups of 128)
// =================================================================
__device__ __forceinline__ void node_body(
    int nb, int t, const float* __restrict__ x, const int* __restrict__ batch,
    const float* __restrict__ Wl, const float* __restrict__ beta,
    int l, int use_x, int bn_in) {
    __shared__ __align__(16) float hs[2][64][16];
    __shared__ int bsm[2][16];
    const float* hin = use_x ? x : g_h;
    int g = t >> 7, tt = t & 127;
    int node0 = nb * 32 + g * 16;
#pragma unroll
    for (int i = tt; i < 16 * 64; i += 128) {
        int n = i >> 6, k = i & 63;
        float v = hin[(node0 + n) * DIN + k];
        if (bn_in) {
            v = (v - g_mu[k]) * g_scale[k] + beta[k];
            v = v > 0.f ? v : 0.f;
        }
        hs[g][k][n] = v;
    }
    if (tt < 16) bsm[g][tt] = batch[node0 + tt];
    __syncthreads();

    int m = tt;
    float acc[16];
#pragma unroll
    for (int n = 0; n < 16; n++)
        acc[n] = g_ins_xl[(l * BB + bsm[g][n]) * 128 + m];

    const float* Wtop = Wl + l * 16384;
#pragma unroll 4
    for (int k = 0; k < 64; k++) {
        float w = Wtop[k * 128 + m];
        float4 a = *(const float4*)&hs[g][k][0];
        float4 b = *(const float4*)&hs[g][k][4];
        float4 c = *(const float4*)&hs[g][k][8];
        float4 d = *(const float4*)&hs[g][k][12];
        acc[0]  += a.x * w; acc[1]  += a.y * w; acc[2]  += a.z * w; acc[3]  += a.w * w;
        acc[4]  += b.x * w; acc[5]  += b.y * w; acc[6]  += b.z * w; acc[7]  += b.w * w;
        acc[8]  += c.x * w; acc[9]  += c.y * w; acc[10] += c.z * w; acc[11] += c.w * w;
        acc[12] += d.x * w; acc[13] += d.y * w; acc[14] += d.z * w; acc[15] += d.w * w;
    }
#pragma unroll
    for (int n = 0; n < 16; n++)
        g_xlh[(node0 + n) * 128 + m] = __float2half_rn(acc[n]);

    if (tt < 64) {
        int n  = tt >> 2;
        int q  = tt & 3;
        int ta = q >> 1;
        int hh = q & 1;
        float a2 = 0.f;
        const float* w = &g_wa[((l * 3 + ta) * 128) * HH + hh];
#pragma unroll 8
        for (int k = 0; k < 64; k++)
            a2 += hs[g][k][n] * w[k * HH];
        a2 += g_ins_a[((l * 3 + ta) * BB + bsm[g][n]) * HH + hh];
        float* dst = (ta == 0) ? g_al : g_ar;
        dst[(node0 + n) * HH + hh] = a2;
    }
}

// standalone node kernel (layer 1)
__global__ __launch_bounds__(256) void node_kernel(
    const float* __restrict__ x, const int* __restrict__ batch,
    const float* __restrict__ Wl, const float* __restrict__ beta,
    int l, int use_x, int bn_in) {
    node_body(blockIdx.x, threadIdx.x, x, batch, Wl, beta, l, use_x, bn_in);
}

// =================================================================
// megaA: [0,625) node(0) | [625,1875) place | [1875,41875) edge_pre
// (no sort here — sort would force local-array register pressure on all paths)
// =================================================================
__global__ __launch_bounds__(256) void megaA_kernel(
    const float* __restrict__ x, const int* __restrict__ batch,
    const float* __restrict__ Wl, const int* __restrict__ ei,
    const float* __restrict__ ea) {
    int bid = blockIdx.x;
    int t = threadIdx.x;
    if (bid < 625) {
        node_body(bid, t, x, batch, Wl, (const float*)0, 0, 1, 0);
    } else if (bid < 1875) {
        int e = (bid - 625) * 256 + t;
        int d = ei[EE + e];
        int pos = atomicAdd(&g_cur[d], 1);
        g_csr[pos] = e;
    } else {
        // ---- edge_pre: ae dots + ins terms, both layers ----
        int warp = t >> 5, lane = t & 31;
        int e = (bid - 1875) * 8 + warp;
        float ea0 = ea[e * 64 + lane];
        float ea1 = ea[e * 64 + 32 + lane];
        float p[LL][HH];
#pragma unroll
        for (int l = 0; l < LL; l++) {
            const float* w = &g_wa[((l * 3 + 2) * 128) * HH];
#pragma unroll
            for (int h = 0; h < HH; h++)
                p[l][h] = ea0 * w[lane * 2 + h] + ea1 * w[(lane + 32) * 2 + h];
        }
#pragma unroll
        for (int off = 16; off; off >>= 1)
#pragma unroll
            for (int l = 0; l < LL; l++)
#pragma unroll
                for (int h = 0; h < HH; h++)
                    p[l][h] += __shfl_xor_sync(0xffffffffu, p[l][h], off);
        if (lane == 0) {
            int s = ei[e];
            int b = batch[s];
#pragma unroll
            for (int l = 0; l < LL; l++) {
                float2 v;
                v.x = p[l][0] + g_ins_a[((l * 3 + 2) * BB + b) * HH + 0];
                v.y = p[l][1] + g_ins_a[((l * 3 + 2) * BB + b) * HH + 1];
                *(float2*)&g_pe[(l * EE + e) * 2] = v;
            }
        }
    }
}

// ---------------- canonicalize bucket order: warp rank sort ----------------
__global__ __launch_bounds__(256) void sort_kernel() {
    int warp = threadIdx.x >> 5, lane = threadIdx.x & 31;
    int n = blockIdx.x * 8 + warp;
    if (n >= NN) return;
    int s0 = g_start[n], s1 = g_start[n + 1];
    int d = s1 - s0;
    if (d <= 1) return;
    if (d <= 32) {
        int v = (lane < d) ? g_csr[s0 + lane] : 0x7fffffff;
        int rank = 0;
#pragma unroll
        for (int j = 0; j < 32; j++) {
            int u = __shfl_sync(0xffffffffu, v, j);
            rank += (u < v);
        }
        __syncwarp();
        if (lane < d) g_csr[s0 + rank] = v;
    } else if (lane == 0) {
        for (int i = s0 + 1; i < s1; i++) {
            int v = g_csr[i];
            int j = i - 1;
            while (j >= s0 && g_csr[j] > v) { g_csr[j + 1] = g_csr[j]; j--; }
            g_csr[j + 1] = v;
        }
    }
}

// =================================================================
// gather: 512 thr = 16 warps = 16 nodes/block; fused logit+exp+softmax+agg
//         (+ deterministic BN partials when do_bn_out)
// =================================================================
__global__ __launch_bounds__(512) void gather_kernel(
    const float* __restrict__ x, const float* __restrict__ bias,
    const float* __restrict__ beta, float* __restrict__ dout,
    const int* __restrict__ ei, int l, int use_x, int bn_in, int do_bn_out) {
    __shared__ float so[16][64];
    __shared__ float sq[16][64];
    int t = threadIdx.x;
    int warp = t >> 5, lane = t & 31;
    int n = blockIdx.x * 16 + warp;
    const float* hin = use_x ? x : g_h;
    float* hout = do_bn_out ? g_h : dout;
    int s0 = g_start[n], s1 = g_start[n + 1];
    float2 arn = *(const float2*)&g_ar[n * 2];

    int i = s0 + lane;
    int src = 0;
    float ex0 = 0.f, ex1 = 0.f;
    if (i < s1) {
        int e = g_csr[i];
        src = ei[e];
        float2 pe = *(const float2*)&g_pe[(l * EE + e) * 2];
        float2 al2 = *(const float2*)&g_al[src * 2];
        float a0 = pe.x + al2.x + arn.x;
        float a1 = pe.y + al2.y + arn.y;
        a0 = a0 > 0.f ? a0 : SLOPE * a0;
        a1 = a1 > 0.f ? a1 : SLOPE * a1;
        ex0 = __expf(a0);
        ex1 = __expf(a1);
    }
    float ss0 = ex0, ss1 = ex1;
    for (int base = s0 + 32; base < s1; base += 32) {   // rare (deg > 32)
        int j = base + lane;
        if (j < s1) {
            int e = g_csr[j];
            int sj = ei[e];
            float2 pe = *(const float2*)&g_pe[(l * EE + e) * 2];
            float2 al2 = *(const float2*)&g_al[sj * 2];
            float a0 = pe.x + al2.x + arn.x;
            float a1 = pe.y + al2.y + arn.y;
            a0 = a0 > 0.f ? a0 : SLOPE * a0;
            a1 = a1 > 0.f ? a1 : SLOPE * a1;
            ss0 += __expf(a0);
            ss1 += __expf(a1);
        }
    }
#pragma unroll
    for (int off = 16; off; off >>= 1) {
        ss0 += __shfl_xor_sync(0xffffffffu, ss0, off);
        ss1 += __shfl_xor_sync(0xffffffffu, ss1, off);
    }
    float inv0 = 0.5f / (ss0 + 1e-16f);
    float inv1 = 0.5f / (ss1 + 1e-16f);

    // prescale once (saves 2 FMUL per edge-iter in the broadcast loop)
    float w0p = ex0 * inv0;
    float w1p = ex1 * inv1;

    float4 acc = make_float4(0.f, 0.f, 0.f, 0.f);
    bool head0 = (lane < 16);
    int dc = s1 - s0; if (dc > 32) dc = 32;
    for (int k = 0; k < dc; k++) {
        float w0 = __shfl_sync(0xffffffffu, w0p, k);
        float w1 = __shfl_sync(0xffffffffu, w1p, k);
        int sj   = __shfl_sync(0xffffffffu, src, k);
        float w = head0 ? w0 : w1;
        uint2 u = ((const uint2*)(g_xlh + sj * 128))[lane];
        float2 f0 = __half22float2(*(__half2*)&u.x);
        float2 f1 = __half22float2(*(__half2*)&u.y);
        acc.x += w * f0.x; acc.y += w * f0.y; acc.z += w * f1.x; acc.w += w * f1.y;
    }
    for (int base = s0 + 32; base < s1; base += 32) {   // rare tail
        int j = base + lane;
        int src2 = 0;
        float e0 = 0.f, e1 = 0.f;
        if (j < s1) {
            int e = g_csr[j];
            src2 = ei[e];
            float2 pe = *(const float2*)&g_pe[(l * EE + e) * 2];
            float2 al2 = *(const float2*)&g_al[src2 * 2];
            float a0 = pe.x + al2.x + arn.x;
            float a1 = pe.y + al2.y + arn.y;
            a0 = a0 > 0.f ? a0 : SLOPE * a0;
            a1 = a1 > 0.f ? a1 : SLOPE * a1;
            e0 = __expf(a0) * inv0;
            e1 = __expf(a1) * inv1;
        }
        int cnt = s1 - base; if (cnt > 32) cnt = 32;
        for (int k = 0; k < cnt; k++) {
            float w0 = __shfl_sync(0xffffffffu, e0, k);
            float w1 = __shfl_sync(0xffffffffu, e1, k);
            int sj   = __shfl_sync(0xffffffffu, src2, k);
            float w = head0 ? w0 : w1;
            uint2 u = ((const uint2*)(g_xlh + sj * 128))[lane];
            float2 f0 = __half22float2(*(__half2*)&u.x);
            float2 f1 = __half22float2(*(__half2*)&u.y);
            acc.x += w * f0.x; acc.y += w * f0.y; acc.z += w * f1.x; acc.w += w * f1.y;
        }
    }

    // head mean: lane L + lane L+16 -> channels 4L..4L+3
    acc.x += __shfl_down_sync(0xffffffffu, acc.x, 16);
    acc.y += __shfl_down_sync(0xffffffffu, acc.y, 16);
    acc.z += __shfl_down_sync(0xffffffffu, acc.z, 16);
    acc.w += __shfl_down_sync(0xffffffffu, acc.w, 16);

    if (lane < 16) {
        float4 h4 = ((const float4*)(hin + n * DIN))[lane];
        if (bn_in) {
            float4 mu = ((const float4*)g_mu)[lane];
            float4 sc = ((const float4*)g_scale)[lane];
            float4 be = ((const float4*)beta)[lane];
            h4.x = (h4.x - mu.x) * sc.x + be.x; h4.x = h4.x > 0.f ? h4.x : 0.f;
            h4.y = (h4.y - mu.y) * sc.y + be.y; h4.y = h4.y > 0.f ? h4.y : 0.f;
            h4.z = (h4.z - mu.z) * sc.z + be.z; h4.z = h4.z > 0.f ? h4.z : 0.f;
            h4.w = (h4.w - mu.w) * sc.w + be.w; h4.w = h4.w > 0.f ? h4.w : 0.f;
        }
        float4 b4 = ((const float4*)(bias + l * CC))[lane];
        float4 o;
        o.x = acc.x + b4.x + h4.x;
        o.y = acc.y + b4.y + h4.y;
        o.z = acc.z + b4.z + h4.z;
        o.w = acc.w + b4.w + h4.w;
        ((float4*)(hout + n * DIN))[lane] = o;
        if (do_bn_out) {
            so[warp][lane * 4 + 0] = o.x; sq[warp][lane * 4 + 0] = o.x * o.x;
            so[warp][lane * 4 + 1] = o.y; sq[warp][lane * 4 + 1] = o.y * o.y;
            so[warp][lane * 4 + 2] = o.z; sq[warp][lane * 4 + 2] = o.z * o.z;
            so[warp][lane * 4 + 3] = o.w; sq[warp][lane * 4 + 3] = o.w * o.w;
        }
    }
    if (do_bn_out) {
        __syncthreads();
        if (t < 64) {
            float su = 0.f, s2 = 0.f;
#pragma unroll
            for (int w = 0; w < 16; w++) { su += so[w][t]; s2 += sq[w][t]; }
            g_bnp[blockIdx.x * 64 + t]  = su;
            g_bnp2[blockIdx.x * 64 + t] = s2;
        }
    }
}

// ---------------- BN finalize (single block, deterministic) ----------------
__global__ __launch_bounds__(256) void bn_finalize(const float* __restrict__ gamma) {
    __shared__ float s1[256], s2m[256];
    int t = threadIdx.x;
    int c = t & 63, slot = t >> 6;
    float su = 0.f, sqv = 0.f;
    for (int b = slot; b < GB; b += 4) {
        su  += g_bnp[b * 64 + c];
        sqv += g_bnp2[b * 64 + c];
    }
    s1[t] = su; s2m[t] = sqv;
    __syncthreads();
    if (t < 64) {
        float S  = s1[t] + s1[t + 64] + s1[t + 128] + s1[t + 192];
        float S2 = s2m[t] + s2m[t + 64] + s2m[t + 128] + s2m[t + 192];
        float mu = S / (float)NN;
        float var = S2 / (float)NN - mu * mu;
        g_mu[t] = mu;
        g_scale[t] = gamma[t] * rsqrtf(var + EPSBN);
    }
}

extern "C" void kernel_launch(void* const* d_in, const int* in_sizes, int n_in,
                              void* d_out, int out_size) {
    const float* x     = (const float*)d_in[0];
    const int*   ei    = (const int*)  d_in[1];
    const float* ea    = (const float*)d_in[2];
    const float* ins   = (const float*)d_in[3];
    const int*   batch = (const int*)  d_in[4];
    const float* Wl    = (const float*)d_in[5];
    const float* We    = (const float*)d_in[6];
    const float* attl  = (const float*)d_in[7];
    const float* attr_ = (const float*)d_in[8];
    const float* atte  = (const float*)d_in[9];
    const float* bias  = (const float*)d_in[10];
    const float* gamma = (const float*)d_in[11];
    const float* beta  = (const float*)d_in[12];
    float* out = (float*)d_out;

    prep_kernel<<<1390, 256>>>(Wl, We, attl, attr_, atte, ins, ei);
    scan_kernel<<<1, 1024>>>();
    megaA_kernel<<<41875, 256>>>(x, batch, Wl, ei, ea);              // node(0) + place + edge_pre
    sort_kernel<<<2500, 256>>>();                                     // canonicalize CSR buckets
    gather_kernel<<<GB, 512>>>(x, bias, beta, out, ei, 0, 1, 0, 1);  // -> g_h + BN partials
    bn_finalize<<<1, 256>>>(gamma);
    node_kernel<<<625, 256>>>(x, batch, Wl, beta, 1, 0, 1);
    gather_kernel<<<GB, 512>>>(x, bias, beta, out, ei, 1, 0, 1, 0);  // -> out
}

// round 11
// speedup vs baseline: 1.1368x; 1.1368x over previous
#include <cuda_runtime.h>
#include <cuda_fp16.h>

#define NN    20000
#define EE    320000
#define BB    128
#define DIN   64
#define HH    2
#define CC    64
#define LL    2
#define SLOPE 0.2f
#define EPSBN 1e-5f
#define GB    1250          // gather blocks (NN/16)
#define SCAN_B 79           // ceil(NN/256)

// ---------------- scratch (device globals; no allocation) ----------------
__device__ __half g_xlh[NN * 128];          // [N][128] node features fp16 (both heads)
__device__ float g_al[NN * HH];
__device__ float g_ar[NN * HH];
__device__ float g_pe[LL * EE * HH];        // ae dot + ins term, both layers
__device__ float g_h[NN * DIN];             // hidden state between layers (pre-BN)
__device__ float g_wa[LL * 3 * 128 * HH];   // folded att vectors [l][{al,ar,ae}][k][h]
__device__ float g_ins_xl[LL * BB * 128];   // ins @ W_l_bottom
__device__ float g_ins_a[LL * 3 * BB * HH]; // ins @ w_{al,ar,ae}_bottom
__device__ int   g_cnt[NN];                 // in-degree histogram
__device__ int   g_start[NN + 1];           // CSR row starts
__device__ int   g_cur[NN];                 // placement cursors
__device__ int   g_csr[EE];                 // edge ids grouped by dst (sorted per bucket)
__device__ int   g_bsum[SCAN_B];            // scan block partials
__device__ float g_bnp[GB * 64];
__device__ float g_bnp2[GB * 64];
__device__ float g_mu[64];
__device__ float g_scale[64];               // gamma * rsqrt(var + eps)

// ---------------- prep 1: fold att vectors through W; zero histogram ----------------
__global__ void prep_weights(const float* __restrict__ Wl, const float* __restrict__ We,
                             const float* __restrict__ attl, const float* __restrict__ attr_,
                             const float* __restrict__ atte) {
    int idx = blockIdx.x * blockDim.x + threadIdx.x;
    if (idx < NN) g_cnt[idx] = 0;
    if (idx >= LL * 3 * 128 * HH) return;
    int l  = idx / (3 * 128 * HH);
    int r  = idx % (3 * 128 * HH);
    int t  = r / (128 * HH);
    int r2 = r % (128 * HH);
    int k  = r2 / HH;
    int h  = r2 % HH;
    const float* W   = (t == 2) ? We : Wl;
    const float* att = (t == 0) ? attl : (t == 1) ? attr_ : atte;
    float acc = 0.f;
#pragma unroll 8
    for (int c = 0; c < CC; c++)
        acc += W[l * 128 * 128 + k * 128 + h * CC + c] * att[l * HH * CC + h * CC + c];
    g_wa[((l * 3 + t) * 128 + k) * HH + h] = acc;
}

// ---------------- prep 2: per-graph instruction terms + dst histogram ----------------
__global__ void prep_ins(const float* __restrict__ ins, const float* __restrict__ Wl,
                         const int* __restrict__ ei) {
    int idx = blockIdx.x * blockDim.x + threadIdx.x;
    const int NXL = LL * BB * 128;
    if (idx < NXL) {
        int l = idx / (BB * 128);
        int r = idx % (BB * 128);
        int b = r / 128;
        int m = r % 128;
        float acc = 0.f;
#pragma unroll 8
        for (int k = 0; k < DIN; k++)
            acc += ins[(l * BB + b) * DIN + k] * Wl[l * 128 * 128 + (64 + k) * 128 + m];
        g_ins_xl[(l * BB + b) * 128 + m] = acc;
    } else if (idx < NXL + LL * 3 * BB * HH) {
        int j  = idx - NXL;
        int l  = j / (3 * BB * HH);
        int r  = j % (3 * BB * HH);
        int t  = r / (BB * HH);
        int r2 = r % (BB * HH);
        int b  = r2 / HH;
        int h  = r2 % HH;
        float acc = 0.f;
#pragma unroll 8
        for (int k = 0; k < DIN; k++)
            acc += ins[(l * BB + b) * DIN + k] * g_wa[((l * 3 + t) * 128 + 64 + k) * HH + h];
        g_ins_a[((l * 3 + t) * BB + b) * HH + h] = acc;
    }
    if (idx < EE) atomicAdd(&g_cnt[ei[EE + idx]], 1);
}

// ---------------- scan phase A: per-block sums ----------------
__global__ __launch_bounds__(256) void scanA() {
    __shared__ int sh[256];
    int t = threadIdx.x;
    int n = blockIdx.x * 256 + t;
    sh[t] = (n < NN) ? g_cnt[n] : 0;
    __syncthreads();
#pragma unroll
    for (int off = 128; off; off >>= 1) {
        if (t < off) sh[t] += sh[t + off];
        __syncthreads();
    }
    if (t == 0) g_bsum[blockIdx.x] = sh[0];
}

// ---------------- scan phase C: block offset (inline) + intra-block scan ----------------
__global__ __launch_bounds__(256) void scanC() {
    __shared__ int sh[256];
    __shared__ int soff;
    int t = threadIdx.x;
    int n = blockIdx.x * 256 + t;
    int v = (n < NN) ? g_cnt[n] : 0;
    if (t < 32) {   // warp 0: offset = sum of preceding block sums
        int off = 0;
        for (int j = t; j < (int)blockIdx.x; j += 32) off += g_bsum[j];
#pragma unroll
        for (int o = 16; o; o >>= 1) off += __shfl_xor_sync(0xffffffffu, off, o);
        if (t == 0) soff = off;
    }
    sh[t] = v;
    __syncthreads();
    for (int off = 1; off < 256; off <<= 1) {
        int u = (t >= off) ? sh[t - off] : 0;
        __syncthreads();
        sh[t] += u;
        __syncthreads();
    }
    if (n < NN) {
        int start = soff + sh[t] - v;   // exclusive within block
        g_start[n] = start;
        g_cur[n] = start;
        if (n == NN - 1) g_start[NN] = start + v;
    }
}

__global__ void place_kernel(const int* __restrict__ ei) {
    int e = blockIdx.x * blockDim.x + threadIdx.x;
    if (e >= EE) return;
    int d = ei[EE + e];
    int pos = atomicAdd(&g_cur[d], 1);
    g_csr[pos] = e;
}

// ---------------- canonicalize bucket order: warp rank sort ----------------
__global__ __launch_bounds__(256) void sort_kernel() {
    int warp = threadIdx.x >> 5, lane = threadIdx.x & 31;
    int n = blockIdx.x * 8 + warp;
    if (n >= NN) return;
    int s0 = g_start[n], s1 = g_start[n + 1];
    int d = s1 - s0;
    if (d <= 1) return;
    if (d <= 32) {
        int v = (lane < d) ? g_csr[s0 + lane] : 0x7fffffff;
        int rank = 0;
#pragma unroll
        for (int j = 0; j < 32; j++) {
            int u = __shfl_sync(0xffffffffu, v, j);
            rank += (u < v);
        }
        __syncwarp();
        if (lane < d) g_csr[s0 + rank] = v;
    } else if (lane == 0) {
        for (int i = s0 + 1; i < s1; i++) {
            int v = g_csr[i];
            int j = i - 1;
            while (j >= s0 && g_csr[j] > v) { g_csr[j + 1] = g_csr[j]; j--; }
            g_csr[j + 1] = v;
        }
    }
}

// ---------------- edge precompute (ONCE): ae dots + ins terms, both layers ----------------
__global__ __launch_bounds__(256) void edge_pre(
    const int* __restrict__ ei, const float* __restrict__ ea,
    const int* __restrict__ batch) {
    int warp = threadIdx.x >> 5, lane = threadIdx.x & 31;
    int e = blockIdx.x * 8 + warp;
    float ea0 = ea[e * 64 + lane];
    float ea1 = ea[e * 64 + 32 + lane];
    float p[LL][HH];
#pragma unroll
    for (int l = 0; l < LL; l++) {
        const float* w = &g_wa[((l * 3 + 2) * 128) * HH];
#pragma unroll
        for (int h = 0; h < HH; h++)
            p[l][h] = ea0 * w[lane * 2 + h] + ea1 * w[(lane + 32) * 2 + h];
    }
#pragma unroll
    for (int off = 16; off; off >>= 1)
#pragma unroll
        for (int l = 0; l < LL; l++)
#pragma unroll
            for (int h = 0; h < HH; h++)
                p[l][h] += __shfl_xor_sync(0xffffffffu, p[l][h], off);
    if (lane == 0) {
        int s = ei[e];
        int b = batch[s];
#pragma unroll
        for (int l = 0; l < LL; l++) {
            float2 v;
            v.x = p[l][0] + g_ins_a[((l * 3 + 2) * BB + b) * HH + 0];
            v.y = p[l][1] + g_ins_a[((l * 3 + 2) * BB + b) * HH + 1];
            *(float2*)&g_pe[(l * EE + e) * 2] = v;
        }
    }
}

// ---------------- node kernel: xl (fp16), al, ar (optional fused BN+relu on input) ----------------
__global__ __launch_bounds__(128) void node_kernel(
    const float* __restrict__ x, const int* __restrict__ batch,
    const float* __restrict__ Wl, const float* __restrict__ beta,
    int l, int use_x, int bn_in) {
    __shared__ __align__(16) float hs[64][16];   // [k][n]
    __shared__ int bsm[16];
    const float* hin = use_x ? x : g_h;
    int node0 = blockIdx.x * 16;
    int t = threadIdx.x;
#pragma unroll
    for (int i = t; i < 16 * 64; i += 128) {
        int n = i >> 6, k = i & 63;
        float v = hin[(node0 + n) * DIN + k];
        if (bn_in) {
            v = (v - g_mu[k]) * g_scale[k] + beta[k];
            v = v > 0.f ? v : 0.f;
        }
        hs[k][n] = v;
    }
    if (t < 16) bsm[t] = batch[node0 + t];
    __syncthreads();

    int m = t;  // output column 0..127
    float acc[16];
#pragma unroll
    for (int n = 0; n < 16; n++)
        acc[n] = g_ins_xl[(l * BB + bsm[n]) * 128 + m];

    const float* Wtop = Wl + l * 128 * 128;
#pragma unroll 4
    for (int k = 0; k < 64; k++) {
        float w = Wtop[k * 128 + m];
        float4 a = *(const float4*)&hs[k][0];
        float4 b = *(const float4*)&hs[k][4];
        float4 c = *(const float4*)&hs[k][8];
        float4 d = *(const float4*)&hs[k][12];
        acc[0]  += a.x * w; acc[1]  += a.y * w; acc[2]  += a.z * w; acc[3]  += a.w * w;
        acc[4]  += b.x * w; acc[5]  += b.y * w; acc[6]  += b.z * w; acc[7]  += b.w * w;
        acc[8]  += c.x * w; acc[9]  += c.y * w; acc[10] += c.z * w; acc[11] += c.w * w;
        acc[12] += d.x * w; acc[13] += d.y * w; acc[14] += d.z * w; acc[15] += d.w * w;
    }
#pragma unroll
    for (int n = 0; n < 16; n++)
        g_xlh[(node0 + n) * 128 + m] = __float2half_rn(acc[n]);

    if (t < 64) {
        int n  = t >> 2;
        int q  = t & 3;
        int ta = q >> 1;
        int hh = q & 1;
        float a2 = 0.f;
        const float* w = &g_wa[((l * 3 + ta) * 128) * HH + hh];
#pragma unroll 8
        for (int k = 0; k < 64; k++)
            a2 += hs[k][n] * w[k * HH];
        a2 += g_ins_a[((l * 3 + ta) * BB + bsm[n]) * HH + hh];
        float* dst = (ta == 0) ? g_al : g_ar;
        dst[(node0 + n) * HH + hh] = a2;
    }
}

// =================================================================
// gather: 512 thr = 16 warps = 16 nodes/block; fused logit+exp+softmax+agg
//         (+ deterministic BN partials when do_bn_out)
// =================================================================
__global__ __launch_bounds__(512) void gather_kernel(
    const float* __restrict__ x, const float* __restrict__ bias,
    const float* __restrict__ beta, float* __restrict__ dout,
    const int* __restrict__ ei, int l, int use_x, int bn_in, int do_bn_out) {
    __shared__ float so[16][64];
    __shared__ float sq[16][64];
    int t = threadIdx.x;
    int warp = t >> 5, lane = t & 31;
    int n = blockIdx.x * 16 + warp;
    const float* hin = use_x ? x : g_h;
    float* hout = do_bn_out ? g_h : dout;
    int s0 = g_start[n], s1 = g_start[n + 1];
    float2 arn = *(const float2*)&g_ar[n * 2];

    int i = s0 + lane;
    int src = 0;
    float ex0 = 0.f, ex1 = 0.f;
    if (i < s1) {
        int e = g_csr[i];
        src = ei[e];
        float2 pe = *(const float2*)&g_pe[(l * EE + e) * 2];
        float2 al2 = *(const float2*)&g_al[src * 2];
        float a0 = pe.x + al2.x + arn.x;
        float a1 = pe.y + al2.y + arn.y;
        a0 = a0 > 0.f ? a0 : SLOPE * a0;
        a1 = a1 > 0.f ? a1 : SLOPE * a1;
        ex0 = __expf(a0);
        ex1 = __expf(a1);
    }
    float ss0 = ex0, ss1 = ex1;
    for (int base = s0 + 32; base < s1; base += 32) {   // rare (deg > 32)
        int j = base + lane;
        if (j < s1) {
            int e = g_csr[j];
            int sj = ei[e];
            float2 pe = *(const float2*)&g_pe[(l * EE + e) * 2];
            float2 al2 = *(const float2*)&g_al[sj * 2];
            float a0 = pe.x + al2.x + arn.x;
            float a1 = pe.y + al2.y + arn.y;
            a0 = a0 > 0.f ? a0 : SLOPE * a0;
            a1 = a1 > 0.f ? a1 : SLOPE * a1;
            ss0 += __expf(a0);
            ss1 += __expf(a1);
        }
    }
#pragma unroll
    for (int off = 16; off; off >>= 1) {
        ss0 += __shfl_xor_sync(0xffffffffu, ss0, off);
        ss1 += __shfl_xor_sync(0xffffffffu, ss1, off);
    }
    float inv0 = 0.5f / (ss0 + 1e-16f);
    float inv1 = 0.5f / (ss1 + 1e-16f);

    // prescale once (saves 2 FMUL per edge-iter in the broadcast loop)
    float w0p = ex0 * inv0;
    float w1p = ex1 * inv1;

    float4 acc = make_float4(0.f, 0.f, 0.f, 0.f);
    bool head0 = (lane < 16);
    int dc = s1 - s0; if (dc > 32) dc = 32;
    for (int k = 0; k < dc; k++) {
        float w0 = __shfl_sync(0xffffffffu, w0p, k);
        float w1 = __shfl_sync(0xffffffffu, w1p, k);
        int sj   = __shfl_sync(0xffffffffu, src, k);
        float w = head0 ? w0 : w1;
        uint2 u = ((const uint2*)(g_xlh + sj * 128))[lane];
        float2 f0 = __half22float2(*(__half2*)&u.x);
        float2 f1 = __half22float2(*(__half2*)&u.y);
        acc.x += w * f0.x; acc.y += w * f0.y; acc.z += w * f1.x; acc.w += w * f1.y;
    }
    for (int base = s0 + 32; base < s1; base += 32) {   // rare tail
        int j = base + lane;
        int src2 = 0;
        float e0 = 0.f, e1 = 0.f;
        if (j < s1) {
            int e = g_csr[j];
            src2 = ei[e];
            float2 pe = *(const float2*)&g_pe[(l * EE + e) * 2];
            float2 al2 = *(const float2*)&g_al[src2 * 2];
            float a0 = pe.x + al2.x + arn.x;
            float a1 = pe.y + al2.y + arn.y;
            a0 = a0 > 0.f ? a0 : SLOPE * a0;
            a1 = a1 > 0.f ? a1 : SLOPE * a1;
            e0 = __expf(a0) * inv0;
            e1 = __expf(a1) * inv1;
        }
        int cnt = s1 - base; if (cnt > 32) cnt = 32;
        for (int k = 0; k < cnt; k++) {
            float w0 = __shfl_sync(0xffffffffu, e0, k);
            float w1 = __shfl_sync(0xffffffffu, e1, k);
            int sj   = __shfl_sync(0xffffffffu, src2, k);
            float w = head0 ? w0 : w1;
            uint2 u = ((const uint2*)(g_xlh + sj * 128))[lane];
            float2 f0 = __half22float2(*(__half2*)&u.x);
            float2 f1 = __half22float2(*(__half2*)&u.y);
            acc.x += w * f0.x; acc.y += w * f0.y; acc.z += w * f1.x; acc.w += w * f1.y;
        }
    }

    // head mean: lane L + lane L+16 -> channels 4L..4L+3
    acc.x += __shfl_down_sync(0xffffffffu, acc.x, 16);
    acc.y += __shfl_down_sync(0xffffffffu, acc.y, 16);
    acc.z += __shfl_down_sync(0xffffffffu, acc.z, 16);
    acc.w += __shfl_down_sync(0xffffffffu, acc.w, 16);

    if (lane < 16) {
        float4 h4 = ((const float4*)(hin + n * DIN))[lane];
        if (bn_in) {
            float4 mu = ((const float4*)g_mu)[lane];
            float4 sc = ((const float4*)g_scale)[lane];
            float4 be = ((const float4*)beta)[lane];
            h4.x = (h4.x - mu.x) * sc.x + be.x; h4.x = h4.x > 0.f ? h4.x : 0.f;
            h4.y = (h4.y - mu.y) * sc.y + be.y; h4.y = h4.y > 0.f ? h4.y : 0.f;
            h4.z = (h4.z - mu.z) * sc.z + be.z; h4.z = h4.z > 0.f ? h4.z : 0.f;
            h4.w = (h4.w - mu.w) * sc.w + be.w; h4.w = h4.w > 0.f ? h4.w : 0.f;
        }
        float4 b4 = ((const float4*)(bias + l * CC))[lane];
        float4 o;
        o.x = acc.x + b4.x + h4.x;
        o.y = acc.y + b4.y + h4.y;
        o.z = acc.z + b4.z + h4.z;
        o.w = acc.w + b4.w + h4.w;
        ((float4*)(hout + n * DIN))[lane] = o;
        if (do_bn_out) {
            so[warp][lane * 4 + 0] = o.x; sq[warp][lane * 4 + 0] = o.x * o.x;
            so[warp][lane * 4 + 1] = o.y; sq[warp][lane * 4 + 1] = o.y * o.y;
            so[warp][lane * 4 + 2] = o.z; sq[warp][lane * 4 + 2] = o.z * o.z;
            so[warp][lane * 4 + 3] = o.w; sq[warp][lane * 4 + 3] = o.w * o.w;
        }
    }
    if (do_bn_out) {
        __syncthreads();
        if (t < 64) {
            float su = 0.f, s2 = 0.f;
#pragma unroll
            for (int w = 0; w < 16; w++) { su += so[w][t]; s2 += sq[w][t]; }
            g_bnp[blockIdx.x * 64 + t]  = su;
            g_bnp2[blockIdx.x * 64 + t] = s2;
        }
    }
}

// ---------------- BN finalize (single block, deterministic) ----------------
__global__ __launch_bounds__(256) void bn_finalize(const float* __restrict__ gamma) {
    __shared__ float s1[256], s2m[256];
    int t = threadIdx.x;
    int c = t & 63, slot = t >> 6;
    float su = 0.f, sqv = 0.f;
    for (int b = slot; b < GB; b += 4) {
        su  += g_bnp[b * 64 + c];
        sqv += g_bnp2[b * 64 + c];
    }
    s1[t] = su; s2m[t] = sqv;
    __syncthreads();
    if (t < 64) {
        float S  = s1[t] + s1[t + 64] + s1[t + 128] + s1[t + 192];
        float S2 = s2m[t] + s2m[t + 64] + s2m[t + 128] + s2m[t + 192];
        float mu = S / (float)NN;
        float var = S2 / (float)NN - mu * mu;
        g_mu[t] = mu;
        g_scale[t] = gamma[t] * rsqrtf(var + EPSBN);
    }
}

extern "C" void kernel_launch(void* const* d_in, const int* in_sizes, int n_in,
                              void* d_out, int out_size) {
    const float* x     = (const float*)d_in[0];
    const int*   ei    = (const int*)  d_in[1];
    const float* ea    = (const float*)d_in[2];
    const float* ins   = (const float*)d_in[3];
    const int*   batch = (const int*)  d_in[4];
    const float* Wl    = (const float*)d_in[5];
    const float* We    = (const float*)d_in[6];
    const float* attl  = (const float*)d_in[7];
    const float* attr_ = (const float*)d_in[8];
    const float* atte  = (const float*)d_in[9];
    const float* bias  = (const float*)d_in[10];
    const float* gamma = (const float*)d_in[11];
    const float* beta  = (const float*)d_in[12];
    float* out = (float*)d_out;

    prep_weights<<<SCAN_B, 256>>>(Wl, We, attl, attr_, atte);          // + zero cnt
    prep_ins<<<EE / 256, 256>>>(ins, Wl, ei);                          // + histogram
    scanA<<<SCAN_B, 256>>>();
    scanC<<<SCAN_B, 256>>>();
    place_kernel<<<EE / 256, 256>>>(ei);
    sort_kernel<<<2500, 256>>>();
    edge_pre<<<EE / 8, 256>>>(ei, ea, batch);

    node_kernel<<<NN / 16, 128>>>(x, batch, Wl, beta, 0, 1, 0);
    gather_kernel<<<GB, 512>>>(x, bias, beta, out, ei, 0, 1, 0, 1);    // -> g_h + BN partials
    bn_finalize<<<1, 256>>>(gamma);
    node_kernel<<<NN / 16, 128>>>(x, batch, Wl, beta, 1, 0, 1);
    gather_kernel<<<GB, 512>>>(x, bias, beta, out, ei, 1, 0, 1, 0);    // -> out
}